// round 4
// baseline (speedup 1.0000x reference)
#include <cuda_runtime.h>
#include <math.h>

#define D_MODEL 1024
#define N_HEADS 16
#define DH      64
#define BATCH   2
#define SEQ     2048
#define BT      (BATCH * SEQ)      // 4096
#define D3      (3 * D_MODEL)      // 3072

// ---------------- scratch (device globals; no allocation allowed) ----------
__device__ float g_qkv[(size_t)3 * BT * D_MODEL];     // [3][B*H][T][DH]
__device__ float g_attn[(size_t)BT * D_MODEL];        // [B,T,D]

// ---------------- helpers ----------------------------------------------------
__device__ __forceinline__ unsigned f2tf32(float f) {
    unsigned r;
    asm("cvt.rna.tf32.f32 %0, %1;" : "=r"(r) : "f"(f));
    return r;
}

__device__ __forceinline__ void mma_tf32(
    float& c0, float& c1, float& c2, float& c3,
    unsigned a0, unsigned a1, unsigned a2, unsigned a3,
    unsigned b0, unsigned b1) {
    asm volatile(
        "mma.sync.aligned.m16n8k8.row.col.f32.tf32.tf32.f32 "
        "{%0,%1,%2,%3}, {%4,%5,%6,%7}, {%8,%9}, {%0,%1,%2,%3};"
        : "+f"(c0), "+f"(c1), "+f"(c2), "+f"(c3)
        : "r"(a0), "r"(a1), "r"(a2), "r"(a3), "r"(b0), "r"(b1));
}

// ---------------- TF32 GEMM: C[M,N] = A[M,K] @ W[N,K]^T ----------------------
// Block 128x128, k-step 16, DOUBLE-BUFFERED smem, one sync per k-step,
// global loads prefetched 2 iterations ahead into registers.
#define KSTEP 16
#define SPAD  20

template <int MODE>
__global__ __launch_bounds__(256, 2) void gemm_tf32_kernel(
    const float* __restrict__ A, const float* __restrict__ W,
    float* __restrict__ C, int M, int N, int K) {
    __shared__ __align__(16) unsigned As[2][128][SPAD];
    __shared__ __align__(16) unsigned Bs[2][128][SPAD];

    const int tid  = threadIdx.x;
    const int lane = tid & 31;
    const int wid  = tid >> 5;
    const int warp_m = wid & 3;
    const int warp_n = wid >> 2;
    const int bm = blockIdx.y * 128;
    const int bn = blockIdx.x * 128;
    const int lr = lane >> 2;
    const int lc = lane & 3;

    // loader mapping: rows tid&63 and +64, col4 = (tid>>6)*4
    const int g_r = tid & 63;
    const int g_c = (tid >> 6) * 4;
    const float* Ap = A + (size_t)(bm + g_r) * K + g_c;
    const float* Wp = W + (size_t)(bn + g_r) * K + g_c;

    float4 ra0, ra1, rb0, rb1;

#define LOAD_T(k0) {                                           \
        ra0 = *(const float4*)&Ap[(k0)];                       \
        ra1 = *(const float4*)&Ap[(size_t)64 * K + (k0)];      \
        rb0 = *(const float4*)&Wp[(k0)];                       \
        rb1 = *(const float4*)&Wp[(size_t)64 * K + (k0)]; }

#define STORE_T(buf) {                                                          \
        *(uint4*)&As[buf][g_r][g_c] =                                           \
            make_uint4(f2tf32(ra0.x), f2tf32(ra0.y), f2tf32(ra0.z), f2tf32(ra0.w)); \
        *(uint4*)&As[buf][g_r + 64][g_c] =                                      \
            make_uint4(f2tf32(ra1.x), f2tf32(ra1.y), f2tf32(ra1.z), f2tf32(ra1.w)); \
        *(uint4*)&Bs[buf][g_r][g_c] =                                           \
            make_uint4(f2tf32(rb0.x), f2tf32(rb0.y), f2tf32(rb0.z), f2tf32(rb0.w)); \
        *(uint4*)&Bs[buf][g_r + 64][g_c] =                                      \
            make_uint4(f2tf32(rb1.x), f2tf32(rb1.y), f2tf32(rb1.z), f2tf32(rb1.w)); }

    float acc[2][8][4];
    #pragma unroll
    for (int i = 0; i < 2; i++)
        #pragma unroll
        for (int j = 0; j < 8; j++)
            #pragma unroll
            for (int c = 0; c < 4; c++) acc[i][j][c] = 0.f;

    LOAD_T(0);
    STORE_T(0);
    LOAD_T(KSTEP);
    __syncthreads();

    const int nk = K / KSTEP;
    for (int i = 0; i < nk; i++) {
        const int buf = i & 1;
        if (i + 1 < nk) STORE_T(buf ^ 1);       // stage tile i+1 (regs already hold it)
        if (i + 2 < nk) LOAD_T((i + 2) * KSTEP); // prefetch tile i+2 (in flight over compute)

        #pragma unroll
        for (int kk = 0; kk < KSTEP; kk += 8) {
            unsigned a[2][4];
            #pragma unroll
            for (int ii = 0; ii < 2; ii++) {
                int m = warp_m * 32 + ii * 16;
                a[ii][0] = As[buf][m + lr][kk + lc];
                a[ii][1] = As[buf][m + lr + 8][kk + lc];
                a[ii][2] = As[buf][m + lr][kk + lc + 4];
                a[ii][3] = As[buf][m + lr + 8][kk + lc + 4];
            }
            #pragma unroll
            for (int j = 0; j < 8; j++) {
                int n = warp_n * 64 + j * 8;
                unsigned b0 = Bs[buf][n + lr][kk + lc];
                unsigned b1 = Bs[buf][n + lr][kk + lc + 4];
                #pragma unroll
                for (int ii = 0; ii < 2; ii++)
                    mma_tf32(acc[ii][j][0], acc[ii][j][1], acc[ii][j][2], acc[ii][j][3],
                             a[ii][0], a[ii][1], a[ii][2], a[ii][3], b0, b1);
            }
        }
        __syncthreads();
    }
#undef LOAD_T
#undef STORE_T

    #pragma unroll
    for (int i = 0; i < 2; i++) {
        #pragma unroll
        for (int j = 0; j < 8; j++) {
            #pragma unroll
            for (int c = 0; c < 4; c++) {
                int m = bm + warp_m * 32 + i * 16 + lr + ((c >= 2) ? 8 : 0);
                int n = bn + warp_n * 64 + j * 8 + 2 * lc + (c & 1);
                if (MODE == 0) {
                    int b = m >> 11;
                    int t = m & (SEQ - 1);
                    int which = n >> 10;
                    int d = n & (D_MODEL - 1);
                    int h = d >> 6;
                    int hd = d & 63;
                    size_t dst = (size_t)which * ((size_t)BT * D_MODEL) +
                                 (((size_t)(b * N_HEADS + h) * SEQ + t) << 6) + hd;
                    C[dst] = acc[i][j][c];
                } else {
                    C[(size_t)m * N + n] = acc[i][j][c];
                }
            }
        }
    }
}

// ---------------- TF32 tensor-core causal flash attention --------------------
// Block: 128 Q rows, 8 warps (16 rows each). K/V tiles 64x64 in SMEM.
// Next K/V tile prefetched into registers, overlapping compute.
#define QT 128
#define KT 64
#define KS_PAD 68
#define VS_PAD 72

__global__ __launch_bounds__(256) void attn_mma_kernel(
    const float* __restrict__ qkv, float* __restrict__ out) {
    __shared__ __align__(16) unsigned Ks[KT][KS_PAD];
    __shared__ __align__(16) unsigned Vs[KT][VS_PAD];

    const int tid  = threadIdx.x;
    const int lane = tid & 31;
    const int wid  = tid >> 5;
    const int lr = lane >> 2;
    const int lc = lane & 3;

    const int bh = blockIdx.y;
    const int qt = (gridDim.x - 1) - blockIdx.x;   // heavy tiles first
    const int q0 = qt * QT;

    const float* Qp = qkv + ((size_t)bh * SEQ + q0) * DH;
    const float* Kp = qkv + (size_t)BT * D_MODEL + (size_t)bh * SEQ * DH;
    const float* Vp = qkv + (size_t)2 * BT * D_MODEL + (size_t)bh * SEQ * DH;

    // ---- Q fragments in registers (scaled by 1/8, exact in tf32) ----
    unsigned qa[8][4];
    {
        const int r0 = wid * 16 + lr;
        #pragma unroll
        for (int kk = 0; kk < 8; kk++) {
            int c = kk * 8 + lc;
            qa[kk][0] = f2tf32(0.125f * Qp[(size_t)r0 * DH + c]);
            qa[kk][1] = f2tf32(0.125f * Qp[(size_t)(r0 + 8) * DH + c]);
            qa[kk][2] = f2tf32(0.125f * Qp[(size_t)r0 * DH + c + 4]);
            qa[kk][3] = f2tf32(0.125f * Qp[(size_t)(r0 + 8) * DH + c + 4]);
        }
    }

    float o[8][4];
    #pragma unroll
    for (int n = 0; n < 8; n++)
        #pragma unroll
        for (int c = 0; c < 4; c++) o[n][c] = 0.f;
    float m0 = -1e30f, m1 = -1e30f, l0 = 0.f, l1 = 0.f;

    const int nkt = 2 * qt + 2;
    const int row0 = q0 + wid * 16 + lr;
    const int row1 = row0 + 8;

    // ---- K/V register prefetch ----
    float4 kr[4], vr[4];
#define LOAD_KV(k0) {                                                    \
        _Pragma("unroll")                                                \
        for (int it = 0; it < 4; it++) {                                 \
            int i = tid + 256 * it;                                      \
            int r = i >> 4;                                              \
            int c = (i & 15) * 4;                                        \
            kr[it] = *(const float4*)&Kp[(size_t)((k0) + r) * DH + c];   \
            vr[it] = *(const float4*)&Vp[(size_t)((k0) + r) * DH + c];   \
        } }

    LOAD_KV(0);

    for (int kt = 0; kt < nkt; kt++) {
        const int k0 = kt * KT;
        __syncthreads();   // prior PV reads of Ks/Vs done before overwrite
        #pragma unroll
        for (int it = 0; it < 4; it++) {
            int i = tid + 256 * it;
            int r = i >> 4;
            int c = (i & 15) * 4;
            *(uint4*)&Ks[r][c] = make_uint4(f2tf32(kr[it].x), f2tf32(kr[it].y),
                                            f2tf32(kr[it].z), f2tf32(kr[it].w));
            *(uint4*)&Vs[r][c] = make_uint4(f2tf32(vr[it].x), f2tf32(vr[it].y),
                                            f2tf32(vr[it].z), f2tf32(vr[it].w));
        }
        __syncthreads();
        if (kt + 1 < nkt) LOAD_KV((kt + 1) * KT);   // in flight over compute below

        // ---- S = (Q/8) @ K^T : per warp 16 x 64 ----
        float s[8][4];
        #pragma unroll
        for (int n = 0; n < 8; n++)
            #pragma unroll
            for (int c = 0; c < 4; c++) s[n][c] = 0.f;

        #pragma unroll
        for (int n = 0; n < 8; n++) {
            #pragma unroll
            for (int kk = 0; kk < 8; kk++) {
                unsigned b0 = Ks[n * 8 + lr][kk * 8 + lc];
                unsigned b1 = Ks[n * 8 + lr][kk * 8 + lc + 4];
                mma_tf32(s[n][0], s[n][1], s[n][2], s[n][3],
                         qa[kk][0], qa[kk][1], qa[kk][2], qa[kk][3], b0, b1);
            }
        }

        // ---- causal mask (only the last two tiles need it) ----
        if (kt >= 2 * qt) {
            #pragma unroll
            for (int n = 0; n < 8; n++) {
                int col0 = k0 + n * 8 + 2 * lc;
                if (col0 > row0)     s[n][0] = -1e30f;
                if (col0 + 1 > row0) s[n][1] = -1e30f;
                if (col0 > row1)     s[n][2] = -1e30f;
                if (col0 + 1 > row1) s[n][3] = -1e30f;
            }
        }

        // ---- online softmax ----
        float mx0 = -1e30f, mx1 = -1e30f;
        #pragma unroll
        for (int n = 0; n < 8; n++) {
            mx0 = fmaxf(mx0, fmaxf(s[n][0], s[n][1]));
            mx1 = fmaxf(mx1, fmaxf(s[n][2], s[n][3]));
        }
        mx0 = fmaxf(mx0, __shfl_xor_sync(0xffffffffu, mx0, 1));
        mx0 = fmaxf(mx0, __shfl_xor_sync(0xffffffffu, mx0, 2));
        mx1 = fmaxf(mx1, __shfl_xor_sync(0xffffffffu, mx1, 1));
        mx1 = fmaxf(mx1, __shfl_xor_sync(0xffffffffu, mx1, 2));

        float mn0 = fmaxf(m0, mx0), mn1 = fmaxf(m1, mx1);
        float alpha0 = __expf(m0 - mn0), alpha1 = __expf(m1 - mn1);
        m0 = mn0; m1 = mn1;

        float sum0 = 0.f, sum1 = 0.f;
        #pragma unroll
        for (int n = 0; n < 8; n++) {
            s[n][0] = __expf(s[n][0] - mn0);
            s[n][1] = __expf(s[n][1] - mn0);
            s[n][2] = __expf(s[n][2] - mn1);
            s[n][3] = __expf(s[n][3] - mn1);
            sum0 += s[n][0] + s[n][1];
            sum1 += s[n][2] + s[n][3];
        }
        sum0 += __shfl_xor_sync(0xffffffffu, sum0, 1);
        sum0 += __shfl_xor_sync(0xffffffffu, sum0, 2);
        sum1 += __shfl_xor_sync(0xffffffffu, sum1, 1);
        sum1 += __shfl_xor_sync(0xffffffffu, sum1, 2);
        l0 = l0 * alpha0 + sum0;
        l1 = l1 * alpha1 + sum1;

        #pragma unroll
        for (int n = 0; n < 8; n++) {
            o[n][0] *= alpha0; o[n][1] *= alpha0;
            o[n][2] *= alpha1; o[n][3] *= alpha1;
        }

        // ---- transpose P accum layout -> A-operand layout (quad shuffles) ---
        const int qbase = lane & ~3;
        const int h0 = qbase + (lc >> 1);
        const int h1 = h0 + 2;
        const bool odd = lc & 1;
        #pragma unroll
        for (int n = 0; n < 8; n++) {
            float t0 = __shfl_sync(0xffffffffu, s[n][0], h0);
            float t1 = __shfl_sync(0xffffffffu, s[n][1], h0);
            float u0 = __shfl_sync(0xffffffffu, s[n][0], h1);
            float u1 = __shfl_sync(0xffffffffu, s[n][1], h1);
            float v0 = __shfl_sync(0xffffffffu, s[n][2], h0);
            float v1 = __shfl_sync(0xffffffffu, s[n][3], h0);
            float w0 = __shfl_sync(0xffffffffu, s[n][2], h1);
            float w1 = __shfl_sync(0xffffffffu, s[n][3], h1);
            s[n][0] = __uint_as_float(f2tf32(odd ? t1 : t0));
            s[n][1] = __uint_as_float(f2tf32(odd ? v1 : v0));
            s[n][2] = __uint_as_float(f2tf32(odd ? u1 : u0));
            s[n][3] = __uint_as_float(f2tf32(odd ? w1 : w0));
        }

        // ---- O += P @ V ----
        #pragma unroll
        for (int d = 0; d < 8; d++) {
            #pragma unroll
            for (int kk = 0; kk < 8; kk++) {
                unsigned b0 = Vs[kk * 8 + lc][d * 8 + lr];
                unsigned b1 = Vs[kk * 8 + lc + 4][d * 8 + lr];
                mma_tf32(o[d][0], o[d][1], o[d][2], o[d][3],
                         __float_as_uint(s[kk][0]), __float_as_uint(s[kk][1]),
                         __float_as_uint(s[kk][2]), __float_as_uint(s[kk][3]),
                         b0, b1);
            }
        }
    }
#undef LOAD_KV

    // ---- epilogue: normalize and store to g_attn [B,T,D] ----
    const int b = bh >> 4;
    const int h = bh & 15;
    const float inv0 = 1.f / l0;
    const float inv1 = 1.f / l1;
    #pragma unroll
    for (int n = 0; n < 8; n++) {
        int d = h * DH + n * 8 + 2 * lc;
        float2 r0v = make_float2(o[n][0] * inv0, o[n][1] * inv0);
        float2 r1v = make_float2(o[n][2] * inv1, o[n][3] * inv1);
        *(float2*)&out[((size_t)(b * SEQ + row0)) * D_MODEL + d] = r0v;
        *(float2*)&out[((size_t)(b * SEQ + row1)) * D_MODEL + d] = r1v;
    }
}

// ---------------- launch ------------------------------------------------------
extern "C" void kernel_launch(void* const* d_in, const int* in_sizes, int n_in,
                              void* d_out, int out_size) {
    const float* x     = (const float*)d_in[0];
    const float* W_in  = (const float*)d_in[1];
    const float* W_out = (const float*)d_in[2];
    float* out = (float*)d_out;

    float *qkv, *attn;
    cudaGetSymbolAddress((void**)&qkv,  g_qkv);
    cudaGetSymbolAddress((void**)&attn, g_attn);

    // 1. QKV projection (TF32 mma), scattered into [3][B*H][T][DH]
    {
        dim3 grid(D3 / 128, BT / 128);
        gemm_tf32_kernel<0><<<grid, 256>>>(x, W_in, qkv, BT, D3, D_MODEL);
    }

    // 2. causal flash attention (TF32 mma) -> g_attn [B,T,D]
    {
        dim3 grid(SEQ / QT, BATCH * N_HEADS);  // (16, 32)
        attn_mma_kernel<<<grid, 256>>>(qkv, attn);
    }

    // 3. output projection (TF32 mma) -> d_out
    {
        dim3 grid(D_MODEL / 128, BT / 128);
        gemm_tf32_kernel<1><<<grid, 256>>>(attn, W_out, out, BT, D_MODEL, D_MODEL);
    }
}

// round 5
// speedup vs baseline: 1.4329x; 1.4329x over previous
#include <cuda_runtime.h>
#include <math.h>

#define D_MODEL 1024
#define N_HEADS 16
#define DH      64
#define BATCH   2
#define SEQ     2048
#define BT      (BATCH * SEQ)      // 4096
#define D3      (3 * D_MODEL)      // 3072

// ---------------- scratch (device globals; no allocation allowed) ----------
__device__ float g_qkv[(size_t)3 * BT * D_MODEL];     // [3][B*H][T][DH]
__device__ float g_attn[(size_t)BT * D_MODEL];        // [B,T,D]

// ---------------- helpers ----------------------------------------------------
__device__ __forceinline__ unsigned f2tf32(float f) {
    unsigned r;
    asm("cvt.rna.tf32.f32 %0, %1;" : "=r"(r) : "f"(f));
    return r;
}

__device__ __forceinline__ void mma_tf32(
    float& c0, float& c1, float& c2, float& c3,
    unsigned a0, unsigned a1, unsigned a2, unsigned a3,
    unsigned b0, unsigned b1) {
    asm volatile(
        "mma.sync.aligned.m16n8k8.row.col.f32.tf32.tf32.f32 "
        "{%0,%1,%2,%3}, {%4,%5,%6,%7}, {%8,%9}, {%0,%1,%2,%3};"
        : "+f"(c0), "+f"(c1), "+f"(c2), "+f"(c3)
        : "r"(a0), "r"(a1), "r"(a2), "r"(a3), "r"(b0), "r"(b1));
}

// ---------------- TF32 GEMM: C[M,N] = A[M,K] @ W[N,K]^T ----------------------
// Block 128x128, k-step 32, cp.async 2-stage double buffer (raw fp32 in smem,
// tf32 conversion at fragment-load time). ONE __syncthreads per k-step.
#define KSTEP 32
#define SPAD  36
#define STAGE_FLOATS (2 * 128 * SPAD)                  // A + B per stage
#define GEMM_SMEM_BYTES (2 * STAGE_FLOATS * 4)          // 73728

template <int MODE>
__global__ __launch_bounds__(256, 2) void gemm_tf32_kernel(
    const float* __restrict__ A, const float* __restrict__ W,
    float* __restrict__ C, int M, int N, int K) {
    extern __shared__ float smem[];
    unsigned smem_u32;
    asm("{ .reg .u64 t; cvta.to.shared.u64 t, %1; cvt.u32.u64 %0, t; }"
        : "=r"(smem_u32) : "l"(smem));

    const int tid  = threadIdx.x;
    const int lane = tid & 31;
    const int wid  = tid >> 5;
    const int warp_m = wid & 3;
    const int warp_n = wid >> 2;
    const int bm = blockIdx.y * 128;
    const int bn = blockIdx.x * 128;
    const int lr = lane >> 2;
    const int lc = lane & 3;

    // copy mapping: thread handles rows c_row+32*it (it=0..3), 16B at col c_col
    const int c_row = tid >> 3;        // 0..31
    const int c_col = (tid & 7) * 4;   // 0..28
    const float* Abase = A + (size_t)(bm + c_row) * K + c_col;
    const float* Wbase = W + (size_t)(bn + c_row) * K + c_col;

#define COPY_TILE(k0, s) {                                                     \
        unsigned base_ = smem_u32 + (unsigned)((s) * STAGE_FLOATS * 4);        \
        _Pragma("unroll")                                                      \
        for (int it = 0; it < 4; it++) {                                       \
            int row_ = c_row + 32 * it;                                        \
            unsigned da_ = base_ + (unsigned)((row_ * SPAD + c_col) * 4);      \
            const float* sa_ = Abase + (size_t)(32 * it) * K + (k0);           \
            asm volatile("cp.async.cg.shared.global [%0], [%1], 16;"           \
                         :: "r"(da_), "l"(sa_));                               \
            unsigned db_ = base_ +                                             \
                (unsigned)((128 * SPAD + row_ * SPAD + c_col) * 4);            \
            const float* sb_ = Wbase + (size_t)(32 * it) * K + (k0);           \
            asm volatile("cp.async.cg.shared.global [%0], [%1], 16;"           \
                         :: "r"(db_), "l"(sb_));                               \
        }                                                                      \
        asm volatile("cp.async.commit_group;"); }

    float acc[2][8][4];
    #pragma unroll
    for (int i = 0; i < 2; i++)
        #pragma unroll
        for (int j = 0; j < 8; j++)
            #pragma unroll
            for (int c = 0; c < 4; c++) acc[i][j][c] = 0.f;

    COPY_TILE(0, 0);

    const int nk = K / KSTEP;
    for (int i = 0; i < nk; i++) {
        asm volatile("cp.async.wait_group 0;");
        __syncthreads();
        if (i + 1 < nk) COPY_TILE((i + 1) * KSTEP, (i + 1) & 1);

        const float* As_ = smem + (size_t)(i & 1) * STAGE_FLOATS;
        const float* Bs_ = As_ + 128 * SPAD;

        #pragma unroll
        for (int kk = 0; kk < KSTEP; kk += 8) {
            unsigned a[2][4];
            #pragma unroll
            for (int ii = 0; ii < 2; ii++) {
                int m = warp_m * 32 + ii * 16;
                a[ii][0] = f2tf32(As_[(m + lr) * SPAD + kk + lc]);
                a[ii][1] = f2tf32(As_[(m + lr + 8) * SPAD + kk + lc]);
                a[ii][2] = f2tf32(As_[(m + lr) * SPAD + kk + lc + 4]);
                a[ii][3] = f2tf32(As_[(m + lr + 8) * SPAD + kk + lc + 4]);
            }
            #pragma unroll
            for (int j = 0; j < 8; j++) {
                int n = warp_n * 64 + j * 8;
                unsigned b0 = f2tf32(Bs_[(n + lr) * SPAD + kk + lc]);
                unsigned b1 = f2tf32(Bs_[(n + lr) * SPAD + kk + lc + 4]);
                #pragma unroll
                for (int ii = 0; ii < 2; ii++)
                    mma_tf32(acc[ii][j][0], acc[ii][j][1], acc[ii][j][2], acc[ii][j][3],
                             a[ii][0], a[ii][1], a[ii][2], a[ii][3], b0, b1);
            }
        }
    }
#undef COPY_TILE

    #pragma unroll
    for (int i = 0; i < 2; i++) {
        #pragma unroll
        for (int j = 0; j < 8; j++) {
            #pragma unroll
            for (int c = 0; c < 4; c++) {
                int m = bm + warp_m * 32 + i * 16 + lr + ((c >= 2) ? 8 : 0);
                int n = bn + warp_n * 64 + j * 8 + 2 * lc + (c & 1);
                if (MODE == 0) {
                    int b = m >> 11;
                    int t = m & (SEQ - 1);
                    int which = n >> 10;
                    int d = n & (D_MODEL - 1);
                    int h = d >> 6;
                    int hd = d & 63;
                    size_t dst = (size_t)which * ((size_t)BT * D_MODEL) +
                                 (((size_t)(b * N_HEADS + h) * SEQ + t) << 6) + hd;
                    C[dst] = acc[i][j][c];
                } else {
                    C[(size_t)m * N + n] = acc[i][j][c];
                }
            }
        }
    }
}

// ---------------- TF32 tensor-core causal flash attention (R3 version) -------
#define QT 128
#define KT 64
#define KS_PAD 68
#define VS_PAD 72

__global__ __launch_bounds__(256) void attn_mma_kernel(
    const float* __restrict__ qkv, float* __restrict__ out) {
    __shared__ __align__(16) unsigned Ks[KT][KS_PAD];
    __shared__ __align__(16) unsigned Vs[KT][VS_PAD];

    const int tid  = threadIdx.x;
    const int lane = tid & 31;
    const int wid  = tid >> 5;
    const int lr = lane >> 2;
    const int lc = lane & 3;

    const int bh = blockIdx.y;
    const int qt = (gridDim.x - 1) - blockIdx.x;   // heavy tiles first
    const int q0 = qt * QT;

    const float* Qp = qkv + ((size_t)bh * SEQ + q0) * DH;
    const float* Kp = qkv + (size_t)BT * D_MODEL + (size_t)bh * SEQ * DH;
    const float* Vp = qkv + (size_t)2 * BT * D_MODEL + (size_t)bh * SEQ * DH;

    unsigned qa[8][4];
    {
        const int r0 = wid * 16 + lr;
        #pragma unroll
        for (int kk = 0; kk < 8; kk++) {
            int c = kk * 8 + lc;
            qa[kk][0] = f2tf32(0.125f * Qp[(size_t)r0 * DH + c]);
            qa[kk][1] = f2tf32(0.125f * Qp[(size_t)(r0 + 8) * DH + c]);
            qa[kk][2] = f2tf32(0.125f * Qp[(size_t)r0 * DH + c + 4]);
            qa[kk][3] = f2tf32(0.125f * Qp[(size_t)(r0 + 8) * DH + c + 4]);
        }
    }

    float o[8][4];
    #pragma unroll
    for (int n = 0; n < 8; n++)
        #pragma unroll
        for (int c = 0; c < 4; c++) o[n][c] = 0.f;
    float m0 = -1e30f, m1 = -1e30f, l0 = 0.f, l1 = 0.f;

    const int nkt = 2 * qt + 2;
    const int row0 = q0 + wid * 16 + lr;
    const int row1 = row0 + 8;

    for (int kt = 0; kt < nkt; kt++) {
        const int k0 = kt * KT;
        __syncthreads();
        #pragma unroll
        for (int it = 0; it < 4; it++) {
            int i = tid + 256 * it;
            int r = i >> 4;
            int c = (i & 15) * 4;
            float4 kv = *(const float4*)&Kp[(size_t)(k0 + r) * DH + c];
            *(uint4*)&Ks[r][c] = make_uint4(f2tf32(kv.x), f2tf32(kv.y),
                                            f2tf32(kv.z), f2tf32(kv.w));
            float4 vv = *(const float4*)&Vp[(size_t)(k0 + r) * DH + c];
            *(uint4*)&Vs[r][c] = make_uint4(f2tf32(vv.x), f2tf32(vv.y),
                                            f2tf32(vv.z), f2tf32(vv.w));
        }
        __syncthreads();

        float s[8][4];
        #pragma unroll
        for (int n = 0; n < 8; n++)
            #pragma unroll
            for (int c = 0; c < 4; c++) s[n][c] = 0.f;

        #pragma unroll
        for (int n = 0; n < 8; n++) {
            #pragma unroll
            for (int kk = 0; kk < 8; kk++) {
                unsigned b0 = Ks[n * 8 + lr][kk * 8 + lc];
                unsigned b1 = Ks[n * 8 + lr][kk * 8 + lc + 4];
                mma_tf32(s[n][0], s[n][1], s[n][2], s[n][3],
                         qa[kk][0], qa[kk][1], qa[kk][2], qa[kk][3], b0, b1);
            }
        }

        if (kt >= 2 * qt) {
            #pragma unroll
            for (int n = 0; n < 8; n++) {
                int col0 = k0 + n * 8 + 2 * lc;
                if (col0 > row0)     s[n][0] = -1e30f;
                if (col0 + 1 > row0) s[n][1] = -1e30f;
                if (col0 > row1)     s[n][2] = -1e30f;
                if (col0 + 1 > row1) s[n][3] = -1e30f;
            }
        }

        float mx0 = -1e30f, mx1 = -1e30f;
        #pragma unroll
        for (int n = 0; n < 8; n++) {
            mx0 = fmaxf(mx0, fmaxf(s[n][0], s[n][1]));
            mx1 = fmaxf(mx1, fmaxf(s[n][2], s[n][3]));
        }
        mx0 = fmaxf(mx0, __shfl_xor_sync(0xffffffffu, mx0, 1));
        mx0 = fmaxf(mx0, __shfl_xor_sync(0xffffffffu, mx0, 2));
        mx1 = fmaxf(mx1, __shfl_xor_sync(0xffffffffu, mx1, 1));
        mx1 = fmaxf(mx1, __shfl_xor_sync(0xffffffffu, mx1, 2));

        float mn0 = fmaxf(m0, mx0), mn1 = fmaxf(m1, mx1);
        float alpha0 = __expf(m0 - mn0), alpha1 = __expf(m1 - mn1);
        m0 = mn0; m1 = mn1;

        float sum0 = 0.f, sum1 = 0.f;
        #pragma unroll
        for (int n = 0; n < 8; n++) {
            s[n][0] = __expf(s[n][0] - mn0);
            s[n][1] = __expf(s[n][1] - mn0);
            s[n][2] = __expf(s[n][2] - mn1);
            s[n][3] = __expf(s[n][3] - mn1);
            sum0 += s[n][0] + s[n][1];
            sum1 += s[n][2] + s[n][3];
        }
        sum0 += __shfl_xor_sync(0xffffffffu, sum0, 1);
        sum0 += __shfl_xor_sync(0xffffffffu, sum0, 2);
        sum1 += __shfl_xor_sync(0xffffffffu, sum1, 1);
        sum1 += __shfl_xor_sync(0xffffffffu, sum1, 2);
        l0 = l0 * alpha0 + sum0;
        l1 = l1 * alpha1 + sum1;

        #pragma unroll
        for (int n = 0; n < 8; n++) {
            o[n][0] *= alpha0; o[n][1] *= alpha0;
            o[n][2] *= alpha1; o[n][3] *= alpha1;
        }

        const int qbase = lane & ~3;
        const int h0 = qbase + (lc >> 1);
        const int h1 = h0 + 2;
        const bool odd = lc & 1;
        #pragma unroll
        for (int n = 0; n < 8; n++) {
            float t0 = __shfl_sync(0xffffffffu, s[n][0], h0);
            float t1 = __shfl_sync(0xffffffffu, s[n][1], h0);
            float u0 = __shfl_sync(0xffffffffu, s[n][0], h1);
            float u1 = __shfl_sync(0xffffffffu, s[n][1], h1);
            float v0 = __shfl_sync(0xffffffffu, s[n][2], h0);
            float v1 = __shfl_sync(0xffffffffu, s[n][3], h0);
            float w0 = __shfl_sync(0xffffffffu, s[n][2], h1);
            float w1 = __shfl_sync(0xffffffffu, s[n][3], h1);
            s[n][0] = __uint_as_float(f2tf32(odd ? t1 : t0));
            s[n][1] = __uint_as_float(f2tf32(odd ? v1 : v0));
            s[n][2] = __uint_as_float(f2tf32(odd ? u1 : u0));
            s[n][3] = __uint_as_float(f2tf32(odd ? w1 : w0));
        }

        #pragma unroll
        for (int d = 0; d < 8; d++) {
            #pragma unroll
            for (int kk = 0; kk < 8; kk++) {
                unsigned b0 = Vs[kk * 8 + lc][d * 8 + lr];
                unsigned b1 = Vs[kk * 8 + lc + 4][d * 8 + lr];
                mma_tf32(o[d][0], o[d][1], o[d][2], o[d][3],
                         __float_as_uint(s[kk][0]), __float_as_uint(s[kk][1]),
                         __float_as_uint(s[kk][2]), __float_as_uint(s[kk][3]),
                         b0, b1);
            }
        }
    }

    const int b = bh >> 4;
    const int h = bh & 15;
    const float inv0 = 1.f / l0;
    const float inv1 = 1.f / l1;
    #pragma unroll
    for (int n = 0; n < 8; n++) {
        int d = h * DH + n * 8 + 2 * lc;
        float2 r0v = make_float2(o[n][0] * inv0, o[n][1] * inv0);
        float2 r1v = make_float2(o[n][2] * inv1, o[n][3] * inv1);
        *(float2*)&out[((size_t)(b * SEQ + row0)) * D_MODEL + d] = r0v;
        *(float2*)&out[((size_t)(b * SEQ + row1)) * D_MODEL + d] = r1v;
    }
}

// ---------------- launch ------------------------------------------------------
extern "C" void kernel_launch(void* const* d_in, const int* in_sizes, int n_in,
                              void* d_out, int out_size) {
    const float* x     = (const float*)d_in[0];
    const float* W_in  = (const float*)d_in[1];
    const float* W_out = (const float*)d_in[2];
    float* out = (float*)d_out;

    float *qkv, *attn;
    cudaGetSymbolAddress((void**)&qkv,  g_qkv);
    cudaGetSymbolAddress((void**)&attn, g_attn);

    cudaFuncSetAttribute(gemm_tf32_kernel<0>,
                         cudaFuncAttributeMaxDynamicSharedMemorySize, GEMM_SMEM_BYTES);
    cudaFuncSetAttribute(gemm_tf32_kernel<1>,
                         cudaFuncAttributeMaxDynamicSharedMemorySize, GEMM_SMEM_BYTES);

    // 1. QKV projection (TF32 mma + cp.async), scattered into [3][B*H][T][DH]
    {
        dim3 grid(D3 / 128, BT / 128);
        gemm_tf32_kernel<0><<<grid, 256, GEMM_SMEM_BYTES>>>(x, W_in, qkv, BT, D3, D_MODEL);
    }

    // 2. causal flash attention (TF32 mma) -> g_attn [B,T,D]
    {
        dim3 grid(SEQ / QT, BATCH * N_HEADS);  // (16, 32)
        attn_mma_kernel<<<grid, 256>>>(qkv, attn);
    }

    // 3. output projection (TF32 mma + cp.async) -> d_out
    {
        dim3 grid(D_MODEL / 128, BT / 128);
        gemm_tf32_kernel<1><<<grid, 256, GEMM_SMEM_BYTES>>>(attn, W_out, out, BT, D_MODEL, D_MODEL);
    }
}